// round 15
// baseline (speedup 1.0000x reference)
#include <cuda_runtime.h>
#include <cuda_bf16.h>
#include <cstdint>

#define B_  4
#define S_  2048
#define D_  768
#define H_  12
#define M_  (B_ * S_)     // 8192
#define NF_ (3 * D_)      // 2304

// ------------------------- device scratch (no allocs) -----------------------
__device__ __nv_bfloat16  g_xh [(size_t)M_ * D_];    // residual bf16 hi
__device__ __align__(16) uint8_t g_x8h[(size_t)M_ * D_];   // fp8(x)      (2^0)
__device__ __align__(16) uint8_t g_x8l[(size_t)M_ * D_];   // fp8(xl*2^8)
__device__ __nv_bfloat16  g_qh [(size_t)M_ * D_];    // q (pre-scaled) hi/lo
__device__ __nv_bfloat16  g_ql [(size_t)M_ * D_];
__device__ __nv_bfloat16  g_kh [(size_t)M_ * D_];
__device__ __nv_bfloat16  g_kl [(size_t)M_ * D_];
__device__ __nv_bfloat16  g_vth[(size_t)B_ * H_ * 64 * S_];  // v^T hi/lo
__device__ __nv_bfloat16  g_vtl[(size_t)B_ * H_ * 64 * S_];
__device__ __nv_bfloat16  g_zh [(size_t)M_ * D_];    // z bf16 hi
__device__ __align__(16) uint8_t g_z8h[(size_t)M_ * D_];   // fp8(z*2^2)
__device__ __align__(16) uint8_t g_z8l[(size_t)M_ * D_];   // fp8(zl*2^10)
__device__ __nv_bfloat16  g_wth[(size_t)NF_ * D_];   // W_qkv^T bf16 hi
__device__ __align__(16) uint8_t g_w8h[(size_t)NF_ * D_];  // fp8(w*2^5)
__device__ __align__(16) uint8_t g_w8l[(size_t)NF_ * D_];  // fp8(wl*2^13)
__device__ __nv_bfloat16  g_woh[(size_t)D_ * D_];    // W_O^T bf16 hi
__device__ __align__(16) uint8_t g_wo8h[(size_t)D_ * D_];  // fp8(wo*2^5)
__device__ __align__(16) uint8_t g_wo8l[(size_t)D_ * D_];  // fp8(wol*2^13)
__device__ float          g_fb [NF_];

// ------------------------------ PTX helpers --------------------------------
__device__ __forceinline__ uint32_t smem_u32(const void* p) {
    uint32_t a;
    asm("{ .reg .u64 t; cvta.to.shared.u64 t, %1; cvt.u32.u64 %0, t; }"
        : "=r"(a) : "l"(p));
    return a;
}
__device__ __forceinline__ void ldsm_x4(uint32_t* r, uint32_t addr) {
    asm volatile("ldmatrix.sync.aligned.m8n8.x4.shared.b16 {%0,%1,%2,%3}, [%4];"
                 : "=r"(r[0]), "=r"(r[1]), "=r"(r[2]), "=r"(r[3]) : "r"(addr));
}
__device__ __forceinline__ void mma16816(float* c, const uint32_t* a,
                                         uint32_t b0, uint32_t b1) {
    asm volatile(
        "mma.sync.aligned.m16n8k16.row.col.f32.bf16.bf16.f32 "
        "{%0,%1,%2,%3}, {%4,%5,%6,%7}, {%8,%9}, {%0,%1,%2,%3};"
        : "+f"(c[0]), "+f"(c[1]), "+f"(c[2]), "+f"(c[3])
        : "r"(a[0]), "r"(a[1]), "r"(a[2]), "r"(a[3]), "r"(b0), "r"(b1));
}
__device__ __forceinline__ void mma_fp8(float* c, const uint32_t* a,
                                        uint32_t b0, uint32_t b1) {
    asm volatile(
        "mma.sync.aligned.m16n8k32.row.col.f32.e4m3.e4m3.f32 "
        "{%0,%1,%2,%3}, {%4,%5,%6,%7}, {%8,%9}, {%0,%1,%2,%3};"
        : "+f"(c[0]), "+f"(c[1]), "+f"(c[2]), "+f"(c[3])
        : "r"(a[0]), "r"(a[1]), "r"(a[2]), "r"(a[3]), "r"(b0), "r"(b1));
}
__device__ __forceinline__ float ex2f(float x) {
    float y;
    asm("ex2.approx.f32 %0, %1;" : "=f"(y) : "f"(x));
    return y;
}
// pack 2 floats to e4m3 pair; low byte = a
__device__ __forceinline__ uint16_t fp8pack2(float a, float b) {
    uint16_t r;
    asm("cvt.rn.satfinite.e4m3x2.f32 %0, %1, %2;" : "=h"(r) : "f"(b), "f"(a));
    return r;
}
__device__ __forceinline__ void split2(float a, float b, uint32_t& hi, uint32_t& lo) {
    __nv_bfloat16 ha = __float2bfloat16(a), hb = __float2bfloat16(b);
    __nv_bfloat16 la = __float2bfloat16(a - __bfloat162float(ha));
    __nv_bfloat16 lb = __float2bfloat16(b - __bfloat162float(hb));
    __nv_bfloat162 hp = {ha, hb}, lp = {la, lb};
    hi = *(uint32_t*)&hp; lo = *(uint32_t*)&lp;
}
__device__ __forceinline__ void split1(float v, __nv_bfloat16& h, __nv_bfloat16& l) {
    h = __float2bfloat16(v);
    l = __float2bfloat16(v - __bfloat162float(h));
}
#define CP_ASYNC16(dst, src) \
    asm volatile("cp.async.cg.shared.global [%0], [%1], 16;" :: "r"(dst), "l"(src))
#define CP_COMMIT() asm volatile("cp.async.commit_group;" ::: "memory")
#define CP_WAIT(n)  asm volatile("cp.async.wait_group %0;" :: "n"(n) : "memory")

// --------------------------- conversion kernels ----------------------------
__global__ void split_kernel(const float* __restrict__ src) {
    int i8 = (blockIdx.x * 256 + threadIdx.x) * 8;
    if (i8 >= M_ * D_) return;
    float4 v0 = *(const float4*)&src[i8];
    float4 v1 = *(const float4*)&src[i8 + 4];
    float v[8] = {v0.x, v0.y, v0.z, v0.w, v1.x, v1.y, v1.z, v1.w};
    __align__(16) __nv_bfloat16 h[8];
    __align__(8) uint16_t p8h[4], p8l[4];
#pragma unroll
    for (int j = 0; j < 8; j++) h[j] = __float2bfloat16(v[j]);
#pragma unroll
    for (int j = 0; j < 4; j++) {
        float l0 = (v[j*2]   - __bfloat162float(h[j*2]))   * 256.0f;
        float l1 = (v[j*2+1] - __bfloat162float(h[j*2+1])) * 256.0f;
        p8h[j] = fp8pack2(v[j*2], v[j*2+1]);
        p8l[j] = fp8pack2(l0, l1);
    }
    *(uint4*)&g_xh[i8]  = *(uint4*)h;
    *(uint2*)&g_x8h[i8] = *(uint2*)p8h;
    *(uint2*)&g_x8l[i8] = *(uint2*)p8l;
}

__device__ __forceinline__ void trans_tile(const float* src, int src_ld,
                                           __nv_bfloat16* dh, uint8_t* d8h,
                                           uint8_t* d8l, int dst_ld,
                                           int r0, int c0, int base) {
    __shared__ float ts[64 * 65];
    const int tid = threadIdx.x;
#pragma unroll
    for (int it = 0; it < 16; it++) {
        int flat = tid + it * 256;
        int i = flat >> 6, c = flat & 63;
        ts[c * 65 + i] = src[(size_t)(r0 + i) * src_ld + c0 + c];
    }
    __syncthreads();
#pragma unroll
    for (int it = 0; it < 8; it++) {
        int flat = tid + it * 256;
        int c = flat >> 5, rj = flat & 31;
        float v0 = ts[c * 65 + rj * 2], v1 = ts[c * 65 + rj * 2 + 1];
        __nv_bfloat16 h0 = __float2bfloat16(v0), h1 = __float2bfloat16(v1);
        __nv_bfloat162 hp = {h0, h1};
        size_t o = (size_t)(base + c0 + c) * dst_ld + r0 + rj * 2;
        *(uint32_t*)&dh[o] = *(uint32_t*)&hp;
        *(uint16_t*)&d8h[o] = fp8pack2(v0 * 32.0f, v1 * 32.0f);
        float l0 = (v0 - __bfloat162float(h0)) * 8192.0f;
        float l1 = (v1 - __bfloat162float(h1)) * 8192.0f;
        *(uint16_t*)&d8l[o] = fp8pack2(l0, l1);
    }
}

__global__ void trans_qkv_kernel(const float* __restrict__ Wq,
                                 const float* __restrict__ Wk,
                                 const float* __restrict__ Wv,
                                 const float* __restrict__ bq,
                                 const float* __restrict__ bk,
                                 const float* __restrict__ bv) {
    const int by = blockIdx.y;
    const int t = by / H_, h = by % H_;
    if (blockIdx.x == 0 && threadIdx.x < 64) {
        const float* bp = (t == 0) ? bq : (t == 1) ? bk : bv;
        g_fb[t * D_ + h * 64 + threadIdx.x] = bp[h * 64 + threadIdx.x];
    }
    const float* src = ((t == 0) ? Wq : (t == 1) ? Wk : Wv) + (size_t)h * D_ * 64;
    trans_tile(src, 64, g_wth, g_w8h, g_w8l, D_, blockIdx.x * 64, 0, t * D_ + h * 64);
}
__global__ void trans_wo_kernel(const float* __restrict__ Wo) {
    trans_tile(Wo, D_, g_woh, g_wo8h, g_wo8l, D_, blockIdx.x * 64, blockIdx.y * 64, 0);
}

// ------------------- bf16-main + fp8-correction GEMM ------------------------
// Per k32: 2x bf16 k16 MMA (Ah*Bh) + 2x fp8 k32 MMA (A8h*B8l + A8l*B8h).
// fp8 smem rows padded to 48 B (16B-aligned for cp.async + ldmatrix).
// Stage layout (bytes): Ah 0 | Bh 10240 | A8h 20480 | A8l 26624 |
//                       B8h 32768 | B8l 38912 ; stage = 45056.
#define F8P_   6144                // fp8 part bytes (128*48)
#define GSTG_B 45056
template <int MODE>
__global__ __launch_bounds__(256, 1)
void gemm_mma_kernel(const __nv_bfloat16* __restrict__ Ah,
                     const uint8_t* __restrict__ A8h,
                     const uint8_t* __restrict__ A8l,
                     const __nv_bfloat16* __restrict__ Bh,
                     const uint8_t* __restrict__ B8h,
                     const uint8_t* __restrict__ B8l,
                     float* __restrict__ out, int ld_out,
                     const float* __restrict__ bias, float corrScale) {
    extern __shared__ __align__(16) char gsm[];
    const uint32_t sb = smem_u32(gsm);

    const int tid  = threadIdx.x;
    const int wid  = tid >> 5;
    const int lane = tid & 31;
    const int wr   = wid >> 2;
    const int wc   = wid & 3;
    const size_t m0 = blockIdx.y * 128;
    const size_t n0 = blockIdx.x * 128;

    auto load_st = [&](int kt, int st) {
        const int k0 = kt * 32;
        const uint32_t sbase = sb + st * GSTG_B;
#pragma unroll
        for (int it = 0; it < 8; it++) {
            int idx = tid + it * 256;
            if (idx < 1024) {                    // bf16 halves
                int half = idx >> 9;             // 0 Ah, 1 Bh
                int w = idx & 511;
                int row = w >> 2, c = w & 3;
                uint32_t dst = sbase + half * 10240 + row * 80 + c * 16;
                const __nv_bfloat16* src = half
                    ? &Bh[(n0 + row) * D_ + k0 + c * 8]
                    : &Ah[(m0 + row) * D_ + k0 + c * 8];
                CP_ASYNC16(dst, src);
            } else {                             // fp8 parts
                int j = idx - 1024;
                int p = j >> 8;                  // 0 A8h,1 A8l,2 B8h,3 B8l
                int w = j & 255;
                int row = w >> 1, c = w & 1;
                uint32_t dst = sbase + 20480 + p * F8P_ + row * 48 + c * 16;
                const uint8_t* s8 = (p == 0) ? A8h : (p == 1) ? A8l
                                  : (p == 2) ? B8h : B8l;
                const size_t rb = (p < 2) ? m0 : n0;
                CP_ASYNC16(dst, &s8[(rb + row) * D_ + k0 + c * 16]);
            }
        }
        CP_COMMIT();
    };

    float acc [4][4][4] = {};
    float accC[4][4][4] = {};

    const int lrw  = lane & 15;
    const int lcol = (lane >> 4) * 8;            // bf16 element units
    const int bcol = (lane >> 4) * 16;           // fp8 byte units

    load_st(0, 0);

    for (int kt = 0; kt < 24; kt++) {
        const int st = kt & 1;
        if (kt < 23) { load_st(kt + 1, 1 - st); CP_WAIT(1); }
        else         { CP_WAIT(0); }
        __syncthreads();

        const uint32_t s0 = sb + st * GSTG_B;

        // ---- bf16 main: Ah * Bh ----
#pragma unroll
        for (int ks = 0; ks < 2; ks++) {
            const int kb = ks * 16;
            uint32_t aF[4][4], bF[2][4];
#pragma unroll
            for (int mt = 0; mt < 4; mt++)
                ldsm_x4(aF[mt], s0 + (wr * 64 + mt * 16 + lrw) * 80 + (kb + lcol) * 2);
#pragma unroll
            for (int np = 0; np < 2; np++)
                ldsm_x4(bF[np], s0 + 10240 + (wc * 32 + np * 16 + lrw) * 80 + (kb + lcol) * 2);
#pragma unroll
            for (int mt = 0; mt < 4; mt++)
#pragma unroll
                for (int nt = 0; nt < 4; nt++)
                    mma16816(acc[mt][nt], aF[mt], bF[nt >> 1][nt & 1],
                             bF[nt >> 1][(nt & 1) + 2]);
        }

        // ---- fp8 corrections: A8h*B8l + A8l*B8h (k32) ----
        {
            uint32_t a8h[4][4], a8l[4][4], b8h[2][4], b8l[2][4];
#pragma unroll
            for (int mt = 0; mt < 4; mt++) {
                const uint32_t ra = (wr * 64 + mt * 16 + lrw) * 48 + bcol;
                ldsm_x4(a8h[mt], s0 + 20480 + 0 * F8P_ + ra);
                ldsm_x4(a8l[mt], s0 + 20480 + 1 * F8P_ + ra);
            }
#pragma unroll
            for (int np = 0; np < 2; np++) {
                const uint32_t rb = (wc * 32 + np * 16 + lrw) * 48 + bcol;
                ldsm_x4(b8h[np], s0 + 20480 + 2 * F8P_ + rb);
                ldsm_x4(b8l[np], s0 + 20480 + 3 * F8P_ + rb);
            }
#pragma unroll
            for (int mt = 0; mt < 4; mt++)
#pragma unroll
                for (int nt = 0; nt < 4; nt++) {
                    const int np = nt >> 1, ni = nt & 1;
                    mma_fp8(accC[mt][nt], a8h[mt], b8l[np][ni], b8l[np][ni + 2]);
                    mma_fp8(accC[mt][nt], a8l[mt], b8h[np][ni], b8h[np][ni + 2]);
                }
        }
        __syncthreads();
    }

    // merge corrections
#pragma unroll
    for (int mt = 0; mt < 4; mt++)
#pragma unroll
        for (int nt = 0; nt < 4; nt++)
#pragma unroll
            for (int e = 0; e < 4; e++)
                acc[mt][nt][e] = fmaf(accC[mt][nt][e], corrScale, acc[mt][nt][e]);

    const int g = lane >> 2;
    const int cb = (lane & 3) * 2;

    if (MODE == 0) {
#pragma unroll
        for (int mt = 0; mt < 4; mt++)
#pragma unroll
            for (int nt = 0; nt < 4; nt++) {
                const size_t col = n0 + wc * 32 + nt * 8 + cb;
                float2 bv = *(const float2*)&bias[col];
                const size_t r0 = m0 + wr * 64 + mt * 16 + g;
                float2 v0 = {acc[mt][nt][0] + bv.x, acc[mt][nt][1] + bv.y};
                float2 v1 = {acc[mt][nt][2] + bv.x, acc[mt][nt][3] + bv.y};
                *(float2*)&out[r0 * ld_out + col]       = v0;
                *(float2*)&out[(r0 + 8) * ld_out + col] = v1;
            }
    } else {
        const int t  = (int)(n0 / D_);
        const int nn = (int)(n0 - t * D_);
        if (t < 2) {
            __nv_bfloat16* dh = (t == 0) ? g_qh : g_kh;
            __nv_bfloat16* dl = (t == 0) ? g_ql : g_kl;
            const float sc = (t == 0) ? 0.180336880f : 1.0f;   // 0.125*log2e
#pragma unroll
            for (int mt = 0; mt < 4; mt++)
#pragma unroll
                for (int nt = 0; nt < 4; nt++) {
                    const int colw = nn + wc * 32 + nt * 8 + cb;
                    float2 bv = *(const float2*)&bias[n0 + wc * 32 + nt * 8 + cb];
                    const size_t r0 = m0 + wr * 64 + mt * 16 + g;
                    uint32_t h0, l0, h1, l1;
                    split2((acc[mt][nt][0] + bv.x) * sc, (acc[mt][nt][1] + bv.y) * sc, h0, l0);
                    split2((acc[mt][nt][2] + bv.x) * sc, (acc[mt][nt][3] + bv.y) * sc, h1, l1);
                    *(uint32_t*)&dh[r0 * D_ + colw]       = h0;
                    *(uint32_t*)&dl[r0 * D_ + colw]       = l0;
                    *(uint32_t*)&dh[(r0 + 8) * D_ + colw] = h1;
                    *(uint32_t*)&dl[(r0 + 8) * D_ + colw] = l1;
                }
        } else {
            __nv_bfloat16* sm_h = (__nv_bfloat16*)gsm;
            __nv_bfloat16* sm_l = sm_h + 128 * 136;
#pragma unroll
            for (int mt = 0; mt < 4; mt++)
#pragma unroll
                for (int nt = 0; nt < 4; nt++) {
                    const int colw = wc * 32 + nt * 8 + cb;
                    float2 bv = *(const float2*)&bias[n0 + colw];
                    const int rl = wr * 64 + mt * 16 + g;
                    __nv_bfloat16 hh, ll;
                    split1(acc[mt][nt][0] + bv.x, hh, ll);
                    sm_h[colw * 136 + rl] = hh;       sm_l[colw * 136 + rl] = ll;
                    split1(acc[mt][nt][1] + bv.y, hh, ll);
                    sm_h[(colw + 1) * 136 + rl] = hh; sm_l[(colw + 1) * 136 + rl] = ll;
                    split1(acc[mt][nt][2] + bv.x, hh, ll);
                    sm_h[colw * 136 + rl + 8] = hh;       sm_l[colw * 136 + rl + 8] = ll;
                    split1(acc[mt][nt][3] + bv.y, hh, ll);
                    sm_h[(colw + 1) * 136 + rl + 8] = hh; sm_l[(colw + 1) * 136 + rl + 8] = ll;
                }
            __syncthreads();
            const int bidx  = (int)(m0 / S_);
            const int m0loc = (int)(m0 % S_);
#pragma unroll
            for (int it = 0; it < 8; it++) {
                int idx = tid + it * 256;
                int c = idx >> 4, sg = (idx & 15) * 8;
                int he = nn + c;
                int hh2 = he >> 6, e = he & 63;
                size_t ob = ((size_t)(bidx * H_ + hh2) * 64 + e) * S_ + m0loc + sg;
                *(uint4*)&g_vth[ob] = *(uint4*)&sm_h[c * 136 + sg];
                *(uint4*)&g_vtl[ob] = *(uint4*)&sm_l[c * 136 + sg];
            }
        }
    }
}

// ----------- mma.sync bf16x3 causal flash attention (R13 exact) -------------
#define PART_ 4608
#define BUF_  (4 * PART_)
__global__ __launch_bounds__(256, 1) void attn_mma_kernel() {
    extern __shared__ __align__(16) char dsm[];
    __nv_bfloat16* sm = (__nv_bfloat16*)dsm;
    const uint32_t sb = smem_u32(sm);

    const int tid = threadIdx.x, wid = tid >> 5, lane = tid & 31;
    const int qt = gridDim.x - 1 - blockIdx.x;
    const int bh = blockIdx.y;
    const int b = bh / H_, h = bh % H_;
    const int q0 = qt * 128;

#pragma unroll
    for (int it = 0; it < 8; it++) {
        int idx = tid + it * 256;
        int part = idx >> 10;
        int w = idx & 1023;
        int r = w >> 3, c8 = w & 7;
        const __nv_bfloat16* src = part ? g_ql : g_qh;
        *(uint4*)&sm[part * 9216 + r * 72 + c8 * 8] =
            *(const uint4*)&src[(size_t)(b * S_ + q0 + r) * D_ + h * 64 + c8 * 8];
    }
    __syncthreads();

    uint32_t aQh[4][4], aQl[4][4];
    {
        const int row = wid * 16 + (lane & 15);
        const int c8 = (lane >> 4) * 8;
#pragma unroll
        for (int kk = 0; kk < 4; kk++) {
            ldsm_x4(aQh[kk], sb + (row * 72 + kk * 16 + c8) * 2);
            ldsm_x4(aQl[kk], sb + (9216 + row * 72 + kk * 16 + c8) * 2);
        }
    }
    __syncthreads();

    float oacc[8][4] = {};
    float mrun[2] = {-1e30f, -1e30f}, lrun[2] = {0.0f, 0.0f};

    const int lrw = lane & 15;
    const int cb8 = (lane >> 4) * 8;
    const int ntiles = 2 * qt + 2;
    const int mask_from = 2 * qt;

    auto load_tile = [&](int kt, int bs) {
        const int k0 = kt * 64;
#pragma unroll
        for (int it = 0; it < 8; it++) {
            int idx = tid + it * 256;
            int part = idx >> 9;
            int w = idx & 511;
            int row = w >> 3, c8 = w & 7;
            uint32_t dst = sb + (bs * BUF_ + part * PART_ + row * 72 + c8 * 8) * 2;
            const __nv_bfloat16* src;
            if (part < 2) {
                const __nv_bfloat16* base = part ? g_kl : g_kh;
                src = &base[(size_t)(b * S_ + k0 + row) * D_ + h * 64 + c8 * 8];
            } else {
                const __nv_bfloat16* base = (part == 2) ? g_vth : g_vtl;
                src = &base[((size_t)bh * 64 + row) * S_ + k0 + c8 * 8];
            }
            CP_ASYNC16(dst, src);
        }
        CP_COMMIT();
    };

    auto s_compute = [&](float (&sacc)[8][4], int kt) {
        const uint32_t kbase = sb + ((kt & 3) * BUF_) * 2;
#pragma unroll
        for (int nt = 0; nt < 8; nt++)
#pragma unroll
            for (int e = 0; e < 4; e++) sacc[nt][e] = 0.0f;
#pragma unroll
        for (int kk = 0; kk < 4; kk++) {
#pragma unroll
            for (int np = 0; np < 4; np++) {
                uint32_t kbh[4], kbl[4];
                ldsm_x4(kbh, kbase + ((np * 16 + lrw) * 72 + kk * 16 + cb8) * 2);
                ldsm_x4(kbl, kbase + (PART_ + (np * 16 + lrw) * 72 + kk * 16 + cb8) * 2);
#pragma unroll
                for (int ni = 0; ni < 2; ni++) {
                    const int nt = np * 2 + ni;
                    mma16816(sacc[nt], aQh[kk], kbh[ni], kbh[ni + 2]);
                    mma16816(sacc[nt], aQh[kk], kbl[ni], kbl[ni + 2]);
                    mma16816(sacc[nt], aQl[kk], kbh[ni], kbh[ni + 2]);
                }
            }
        }
    };

    auto softmax_pv = [&](float (&sacc)[8][4], int kt) {
        const int k0 = kt * 64;
        if (kt >= mask_from) {
#pragma unroll
            for (int nt = 0; nt < 8; nt++)
#pragma unroll
                for (int e = 0; e < 4; e++) {
                    const int row = q0 + wid * 16 + (lane >> 2) + (e >> 1) * 8;
                    const int col = k0 + nt * 8 + (lane & 3) * 2 + (e & 1);
                    if (col > row) sacc[nt][e] = -1e30f;
                }
        }
#pragma unroll
        for (int rg = 0; rg < 2; rg++) {
            float mloc = -1e30f;
#pragma unroll
            for (int nt = 0; nt < 8; nt++)
                mloc = fmaxf(mloc, fmaxf(sacc[nt][rg * 2], sacc[nt][rg * 2 + 1]));
            mloc = fmaxf(mloc, __shfl_xor_sync(0xffffffffu, mloc, 1));
            mloc = fmaxf(mloc, __shfl_xor_sync(0xffffffffu, mloc, 2));
            const float mnew = fmaxf(mrun[rg], mloc);
            const float alpha = ex2f(mrun[rg] - mnew);
            float lloc = 0.0f;
#pragma unroll
            for (int nt = 0; nt < 8; nt++) {
                sacc[nt][rg * 2]     = ex2f(sacc[nt][rg * 2] - mnew);
                sacc[nt][rg * 2 + 1] = ex2f(sacc[nt][rg * 2 + 1] - mnew);
                lloc += sacc[nt][rg * 2] + sacc[nt][rg * 2 + 1];
            }
            lloc += __shfl_xor_sync(0xffffffffu, lloc, 1);
            lloc += __shfl_xor_sync(0xffffffffu, lloc, 2);
            lrun[rg] = lrun[rg] * alpha + lloc;
            mrun[rg] = mnew;
#pragma unroll
            for (int dt = 0; dt < 8; dt++) {
                oacc[dt][rg * 2]     *= alpha;
                oacc[dt][rg * 2 + 1] *= alpha;
            }
        }

        uint32_t aPh[4][4], aPl[4][4];
#pragma unroll
        for (int k2 = 0; k2 < 4; k2++) {
            split2(sacc[k2 * 2][0],     sacc[k2 * 2][1],     aPh[k2][0], aPl[k2][0]);
            split2(sacc[k2 * 2][2],     sacc[k2 * 2][3],     aPh[k2][1], aPl[k2][1]);
            split2(sacc[k2 * 2 + 1][0], sacc[k2 * 2 + 1][1], aPh[k2][2], aPl[k2][2]);
            split2(sacc[k2 * 2 + 1][2], sacc[k2 * 2 + 1][3], aPh[k2][3], aPl[k2][3]);
        }

        const uint32_t vbase = sb + ((kt & 3) * BUF_ + 2 * PART_) * 2;
#pragma unroll
        for (int k2 = 0; k2 < 4; k2++) {
#pragma unroll
            for (int dp = 0; dp < 4; dp++) {
                uint32_t vbh[4], vbl[4];
                ldsm_x4(vbh, vbase + ((dp * 16 + lrw) * 72 + k2 * 16 + cb8) * 2);
                ldsm_x4(vbl, vbase + (PART_ + (dp * 16 + lrw) * 72 + k2 * 16 + cb8) * 2);
#pragma unroll
                for (int ni = 0; ni < 2; ni++) {
                    const int dt = dp * 2 + ni;
                    mma16816(oacc[dt], aPh[k2], vbh[ni], vbh[ni + 2]);
                    mma16816(oacc[dt], aPh[k2], vbl[ni], vbl[ni + 2]);
                    mma16816(oacc[dt], aPl[k2], vbh[ni], vbh[ni + 2]);
                }
            }
        }
    };

    load_tile(0, 0);
    load_tile(1, 1);

    float sA[8][4], sB[8][4];

    for (int kt2 = 0; kt2 < ntiles; kt2 += 2) {
        CP_WAIT(1);
        __syncthreads();
        if (kt2 + 2 < ntiles) load_tile(kt2 + 2, (kt2 + 2) & 3);
        s_compute(sA, kt2);
        if (kt2 > 0) softmax_pv(sB, kt2 - 1);

        if (kt2 + 2 < ntiles) CP_WAIT(1); else CP_WAIT(0);
        __syncthreads();
        if (kt2 + 3 < ntiles) load_tile(kt2 + 3, (kt2 + 3) & 3);
        s_compute(sB, kt2 + 1);
        softmax_pv(sA, kt2);
    }
    softmax_pv(sB, ntiles - 1);

    // epilogue: z bf16 hi + fp8(z*4) + fp8(zl*1024)
#pragma unroll
    for (int rg = 0; rg < 2; rg++) {
        const float inv = 1.0f / lrun[rg];
        const int row = q0 + wid * 16 + (lane >> 2) + rg * 8;
#pragma unroll
        for (int dt = 0; dt < 8; dt++) {
            const size_t o = (size_t)(b * S_ + row) * D_ + h * 64 + dt * 8 + (lane & 3) * 2;
            float v0 = oacc[dt][rg * 2] * inv;
            float v1 = oacc[dt][rg * 2 + 1] * inv;
            __nv_bfloat16 h0 = __float2bfloat16(v0), h1 = __float2bfloat16(v1);
            __nv_bfloat162 hp = {h0, h1};
            *(uint32_t*)&g_zh[o] = *(uint32_t*)&hp;
            *(uint16_t*)&g_z8h[o] = fp8pack2(v0 * 4.0f, v1 * 4.0f);
            float l0 = (v0 - __bfloat162float(h0)) * 1024.0f;
            float l1 = (v1 - __bfloat162float(h1)) * 1024.0f;
            *(uint16_t*)&g_z8l[o] = fp8pack2(l0, l1);
        }
    }
}

// --------------------------------- launch ----------------------------------
extern "C" void kernel_launch(void* const* d_in, const int* in_sizes, int n_in,
                              void* d_out, int out_size) {
    const float* X  = (const float*)d_in[0];
    const float* Wq = (const float*)d_in[1];
    const float* Wk = (const float*)d_in[2];
    const float* Wv = (const float*)d_in[3];
    const float* Wo = (const float*)d_in[4];
    const float* bq = (const float*)d_in[5];
    const float* bk = (const float*)d_in[6];
    const float* bv = (const float*)d_in[7];
    const float* bo = (const float*)d_in[8];
    float* out = (float*)d_out;

    const int attn_smem = 4 * BUF_ * 2;     // 147456 B
    const int gemm_smem = 2 * GSTG_B;       // 90112 B
    static bool attr_set = false;
    if (!attr_set) {
        cudaFuncSetAttribute(attn_mma_kernel,
                             cudaFuncAttributeMaxDynamicSharedMemorySize, attn_smem);
        cudaFuncSetAttribute(gemm_mma_kernel<0>,
                             cudaFuncAttributeMaxDynamicSharedMemorySize, gemm_smem);
        cudaFuncSetAttribute(gemm_mma_kernel<1>,
                             cudaFuncAttributeMaxDynamicSharedMemorySize, gemm_smem);
        attr_set = true;
    }

    static __nv_bfloat16 *xh = nullptr, *zh, *wth, *woh;
    static uint8_t *x8h, *x8l, *z8h, *z8l, *w8h, *w8l, *wo8h, *wo8l;
    static float *fb;
    if (!xh) {
        cudaGetSymbolAddress((void**)&xh,   g_xh);
        cudaGetSymbolAddress((void**)&x8h,  g_x8h);
        cudaGetSymbolAddress((void**)&x8l,  g_x8l);
        cudaGetSymbolAddress((void**)&zh,   g_zh);
        cudaGetSymbolAddress((void**)&z8h,  g_z8h);
        cudaGetSymbolAddress((void**)&z8l,  g_z8l);
        cudaGetSymbolAddress((void**)&wth,  g_wth);
        cudaGetSymbolAddress((void**)&w8h,  g_w8h);
        cudaGetSymbolAddress((void**)&w8l,  g_w8l);
        cudaGetSymbolAddress((void**)&woh,  g_woh);
        cudaGetSymbolAddress((void**)&wo8h, g_wo8h);
        cudaGetSymbolAddress((void**)&wo8l, g_wo8l);
        cudaGetSymbolAddress((void**)&fb,   g_fb);
    }

    // 1) conversions
    split_kernel<<<(M_ * D_) / (256 * 8), 256>>>(X);
    trans_qkv_kernel<<<dim3(D_ / 64, 3 * H_), 256>>>(Wq, Wk, Wv, bq, bk, bv);
    trans_wo_kernel<<<dim3(D_ / 64, D_ / 64), 256>>>(Wo);

    // 2) fused QKV projection (bf16 main + fp8 corrections, corr 2^-13)
    gemm_mma_kernel<1><<<dim3(NF_ / 128, M_ / 128), 256, gemm_smem>>>(
        xh, x8h, x8l, wth, w8h, w8l, nullptr, 0, fb, 0x1p-13f);

    // 3) causal attention (bf16x3, pipelined)
    attn_mma_kernel<<<dim3(S_ / 128, B_ * H_), 256, attn_smem>>>();

    // 4) output projection (corr 2^-15)
    gemm_mma_kernel<0><<<dim3(D_ / 128, M_ / 128), 256, gemm_smem>>>(
        zh, z8h, z8l, woh, wo8h, wo8l, out, D_, bo, 0x1p-15f);
}

// round 16
// speedup vs baseline: 1.2830x; 1.2830x over previous
#include <cuda_runtime.h>
#include <cuda_bf16.h>
#include <cuda_fp16.h>
#include <cstdint>

#define B_  4
#define S_  2048
#define D_  768
#define H_  12
#define M_  (B_ * S_)     // 8192
#define NF_ (3 * D_)      // 2304

// ------------------------- device scratch (no allocs) -----------------------
__device__ __nv_bfloat16  g_xh [(size_t)M_ * D_];    // residual hi/lo
__device__ __nv_bfloat16  g_xl [(size_t)M_ * D_];
__device__ __half         g_q16[(size_t)M_ * D_];    // q (pre-scaled) fp16
__device__ __half         g_k16[(size_t)M_ * D_];    // k fp16
__device__ __nv_bfloat16  g_vth[(size_t)B_ * H_ * 64 * S_];  // v^T hi/lo
__device__ __nv_bfloat16  g_vtl[(size_t)B_ * H_ * 64 * S_];
__device__ __nv_bfloat16  g_zh [(size_t)M_ * D_];    // attention out hi/lo
__device__ __nv_bfloat16  g_zl [(size_t)M_ * D_];
__device__ __nv_bfloat16  g_wth[(size_t)NF_ * D_];   // W_qkv^T  [n][d] hi/lo
__device__ __nv_bfloat16  g_wtl[(size_t)NF_ * D_];
__device__ __nv_bfloat16  g_woh[(size_t)D_ * D_];    // W_O^T hi/lo
__device__ __nv_bfloat16  g_wol[(size_t)D_ * D_];
__device__ float          g_fb [NF_];                // fused qkv bias

// ------------------------------ PTX helpers --------------------------------
__device__ __forceinline__ uint32_t smem_u32(const void* p) {
    uint32_t a;
    asm("{ .reg .u64 t; cvta.to.shared.u64 t, %1; cvt.u32.u64 %0, t; }"
        : "=r"(a) : "l"(p));
    return a;
}
__device__ __forceinline__ void ldsm_x4(uint32_t* r, uint32_t addr) {
    asm volatile("ldmatrix.sync.aligned.m8n8.x4.shared.b16 {%0,%1,%2,%3}, [%4];"
                 : "=r"(r[0]), "=r"(r[1]), "=r"(r[2]), "=r"(r[3]) : "r"(addr));
}
__device__ __forceinline__ void mma16816(float* c, const uint32_t* a,
                                         uint32_t b0, uint32_t b1) {
    asm volatile(
        "mma.sync.aligned.m16n8k16.row.col.f32.bf16.bf16.f32 "
        "{%0,%1,%2,%3}, {%4,%5,%6,%7}, {%8,%9}, {%0,%1,%2,%3};"
        : "+f"(c[0]), "+f"(c[1]), "+f"(c[2]), "+f"(c[3])
        : "r"(a[0]), "r"(a[1]), "r"(a[2]), "r"(a[3]), "r"(b0), "r"(b1));
}
__device__ __forceinline__ void mma16816h(float* c, const uint32_t* a,
                                          uint32_t b0, uint32_t b1) {
    asm volatile(
        "mma.sync.aligned.m16n8k16.row.col.f32.f16.f16.f32 "
        "{%0,%1,%2,%3}, {%4,%5,%6,%7}, {%8,%9}, {%0,%1,%2,%3};"
        : "+f"(c[0]), "+f"(c[1]), "+f"(c[2]), "+f"(c[3])
        : "r"(a[0]), "r"(a[1]), "r"(a[2]), "r"(a[3]), "r"(b0), "r"(b1));
}
__device__ __forceinline__ float ex2f(float x) {
    float y;
    asm("ex2.approx.f32 %0, %1;" : "=f"(y) : "f"(x));
    return y;
}
__device__ __forceinline__ void split2(float a, float b, uint32_t& hi, uint32_t& lo) {
    __nv_bfloat16 ha = __float2bfloat16(a), hb = __float2bfloat16(b);
    __nv_bfloat16 la = __float2bfloat16(a - __bfloat162float(ha));
    __nv_bfloat16 lb = __float2bfloat16(b - __bfloat162float(hb));
    __nv_bfloat162 hp = {ha, hb}, lp = {la, lb};
    hi = *(uint32_t*)&hp; lo = *(uint32_t*)&lp;
}
__device__ __forceinline__ void split1(float v, __nv_bfloat16& h, __nv_bfloat16& l) {
    h = __float2bfloat16(v);
    l = __float2bfloat16(v - __bfloat162float(h));
}
#define CP_ASYNC16(dst, src) \
    asm volatile("cp.async.cg.shared.global [%0], [%1], 16;" :: "r"(dst), "l"(src))
#define CP_COMMIT() asm volatile("cp.async.commit_group;" ::: "memory")
#define CP_WAIT(n)  asm volatile("cp.async.wait_group %0;" :: "n"(n) : "memory")

// --------------------------- conversion kernels ----------------------------
__global__ void split_kernel(const float* __restrict__ src,
                             __nv_bfloat16* __restrict__ dh,
                             __nv_bfloat16* __restrict__ dl, int n) {
    int i8 = (blockIdx.x * 256 + threadIdx.x) * 8;
    if (i8 >= n) return;
    float4 v0 = *(const float4*)&src[i8];
    float4 v1 = *(const float4*)&src[i8 + 4];
    float v[8] = {v0.x, v0.y, v0.z, v0.w, v1.x, v1.y, v1.z, v1.w};
    __align__(16) __nv_bfloat16 h[8], l[8];
#pragma unroll
    for (int j = 0; j < 8; j++) {
        h[j] = __float2bfloat16(v[j]);
        l[j] = __float2bfloat16(v[j] - __bfloat162float(h[j]));
    }
    *(uint4*)&dh[i8] = *(uint4*)h;
    *(uint4*)&dl[i8] = *(uint4*)l;
}

__device__ __forceinline__ void trans_tile(const float* src, int src_ld,
                                           __nv_bfloat16* dh, __nv_bfloat16* dl,
                                           int dst_ld, int r0, int c0, int base) {
    __shared__ float ts[64 * 65];
    const int tid = threadIdx.x;
#pragma unroll
    for (int it = 0; it < 16; it++) {
        int flat = tid + it * 256;
        int i = flat >> 6, c = flat & 63;
        ts[c * 65 + i] = src[(size_t)(r0 + i) * src_ld + c0 + c];
    }
    __syncthreads();
#pragma unroll
    for (int it = 0; it < 8; it++) {
        int flat = tid + it * 256;
        int c = flat >> 5, rj = flat & 31;
        uint32_t hp, lp;
        split2(ts[c * 65 + rj * 2], ts[c * 65 + rj * 2 + 1], hp, lp);
        size_t o = (size_t)(base + c0 + c) * dst_ld + r0 + rj * 2;
        *(uint32_t*)&dh[o] = hp;
        *(uint32_t*)&dl[o] = lp;
    }
}

__global__ void trans_qkv_kernel(const float* __restrict__ Wq,
                                 const float* __restrict__ Wk,
                                 const float* __restrict__ Wv,
                                 const float* __restrict__ bq,
                                 const float* __restrict__ bk,
                                 const float* __restrict__ bv) {
    const int by = blockIdx.y;
    const int t = by / H_, h = by % H_;
    if (blockIdx.x == 0 && threadIdx.x < 64) {
        const float* bp = (t == 0) ? bq : (t == 1) ? bk : bv;
        g_fb[t * D_ + h * 64 + threadIdx.x] = bp[h * 64 + threadIdx.x];
    }
    const float* src = ((t == 0) ? Wq : (t == 1) ? Wk : Wv) + (size_t)h * D_ * 64;
    trans_tile(src, 64, g_wth, g_wtl, D_, blockIdx.x * 64, 0, t * D_ + h * 64);
}
__global__ void trans_wo_kernel(const float* __restrict__ Wo) {
    trans_tile(Wo, D_, g_woh, g_wol, D_, blockIdx.x * 64, blockIdx.y * 64, 0);
}

// ------------------------ mma.sync bf16x3 GEMM (R13 core) -------------------
// occ 2, cp.async double-buffered. MODE 0: fp32 out + bias.
// MODE 1: q/k written as SINGLE fp16 (q pre-scaled 0.125*log2e); V transposed
// split bf16 hi/lo via smem staging.
#define GP_   5120                 // elements per part (128*40)
#define GSTG_ (4 * GP_)            // elements per stage
#define QSCALE_ 0.180336880f       // 0.125 * log2(e)
template <int MODE>
__global__ __launch_bounds__(256, 2)
void gemm_mma_kernel(const __nv_bfloat16* __restrict__ Ah,
                     const __nv_bfloat16* __restrict__ Al,
                     const __nv_bfloat16* __restrict__ Bh,
                     const __nv_bfloat16* __restrict__ Bl,
                     float* __restrict__ out, int ld_out,
                     const float* __restrict__ bias) {
    extern __shared__ __align__(16) char gsm[];
    const uint32_t sb = smem_u32(gsm);

    const int tid  = threadIdx.x;
    const int wid  = tid >> 5;
    const int lane = tid & 31;
    const int wr   = wid >> 2;
    const int wc   = wid & 3;
    const size_t m0 = blockIdx.y * 128;
    const size_t n0 = blockIdx.x * 128;

    const __nv_bfloat16* srcs[4] = {Ah, Al, Bh, Bl};
    const size_t rbase[4] = {m0, m0, n0, n0};

    auto load_st = [&](int kt, int st) {
        const int k0 = kt * 32;
#pragma unroll
        for (int it = 0; it < 8; it++) {
            int idx = tid + it * 256;
            int part = idx >> 9;
            int w = idx & 511;
            int row = w >> 2, c8 = w & 3;
            uint32_t dst = sb + (st * GSTG_ + part * GP_ + row * 40 + c8 * 8) * 2;
            const __nv_bfloat16* src =
                &srcs[part][(rbase[part] + row) * D_ + k0 + c8 * 8];
            CP_ASYNC16(dst, src);
        }
        CP_COMMIT();
    };

    float acc[4][4][4] = {};

    const int lrow = lane & 15;
    const int lcol = (lane >> 4) * 8;

    load_st(0, 0);

    for (int kt = 0; kt < 24; kt++) {
        const int st = kt & 1;
        if (kt < 23) { load_st(kt + 1, 1 - st); CP_WAIT(1); }
        else         { CP_WAIT(0); }
        __syncthreads();

        const uint32_t s0 = sb + (st * GSTG_) * 2;
#pragma unroll
        for (int ks = 0; ks < 2; ks++) {
            const int kb = ks * 16;
            const uint32_t arow = s0 + ((wr * 64 + lrow) * 40 + kb + lcol) * 2;
            const uint32_t brow = s0 + ((wc * 32 + lrow) * 40 + kb + lcol) * 2;

            uint32_t aF[4][4], bFh[2][4], bF2[2][4];
#pragma unroll
            for (int mt = 0; mt < 4; mt++)
                ldsm_x4(aF[mt], arow + (0 * GP_ + mt * 16 * 40) * 2);
#pragma unroll
            for (int np = 0; np < 2; np++)
                ldsm_x4(bFh[np], brow + (2 * GP_ + np * 16 * 40) * 2);
#pragma unroll
            for (int mt = 0; mt < 4; mt++)
#pragma unroll
                for (int nt = 0; nt < 4; nt++)
                    mma16816(acc[mt][nt], aF[mt], bFh[nt >> 1][nt & 1],
                             bFh[nt >> 1][(nt & 1) + 2]);
#pragma unroll
            for (int np = 0; np < 2; np++)
                ldsm_x4(bF2[np], brow + (3 * GP_ + np * 16 * 40) * 2);
#pragma unroll
            for (int mt = 0; mt < 4; mt++)
#pragma unroll
                for (int nt = 0; nt < 4; nt++)
                    mma16816(acc[mt][nt], aF[mt], bF2[nt >> 1][nt & 1],
                             bF2[nt >> 1][(nt & 1) + 2]);
#pragma unroll
            for (int mt = 0; mt < 4; mt++)
                ldsm_x4(aF[mt], arow + (1 * GP_ + mt * 16 * 40) * 2);
#pragma unroll
            for (int mt = 0; mt < 4; mt++)
#pragma unroll
                for (int nt = 0; nt < 4; nt++)
                    mma16816(acc[mt][nt], aF[mt], bFh[nt >> 1][nt & 1],
                             bFh[nt >> 1][(nt & 1) + 2]);
        }
        __syncthreads();
    }

    const int g = lane >> 2;
    const int cb = (lane & 3) * 2;

    if (MODE == 0) {
#pragma unroll
        for (int mt = 0; mt < 4; mt++)
#pragma unroll
            for (int nt = 0; nt < 4; nt++) {
                const size_t col = n0 + wc * 32 + nt * 8 + cb;
                float2 bv = *(const float2*)&bias[col];
                const size_t r0 = m0 + wr * 64 + mt * 16 + g;
                float2 v0 = {acc[mt][nt][0] + bv.x, acc[mt][nt][1] + bv.y};
                float2 v1 = {acc[mt][nt][2] + bv.x, acc[mt][nt][3] + bv.y};
                *(float2*)&out[r0 * ld_out + col]       = v0;
                *(float2*)&out[(r0 + 8) * ld_out + col] = v1;
            }
    } else {
        const int t  = (int)(n0 / D_);
        const int nn = (int)(n0 - t * D_);
        if (t < 2) {
            __half* dq = (t == 0) ? g_q16 : g_k16;
            const float sc = (t == 0) ? QSCALE_ : 1.0f;
#pragma unroll
            for (int mt = 0; mt < 4; mt++)
#pragma unroll
                for (int nt = 0; nt < 4; nt++) {
                    const int colw = nn + wc * 32 + nt * 8 + cb;
                    float2 bv = *(const float2*)&bias[n0 + wc * 32 + nt * 8 + cb];
                    const size_t r0 = m0 + wr * 64 + mt * 16 + g;
                    __half2 h0 = __floats2half2_rn((acc[mt][nt][0] + bv.x) * sc,
                                                   (acc[mt][nt][1] + bv.y) * sc);
                    __half2 h1 = __floats2half2_rn((acc[mt][nt][2] + bv.x) * sc,
                                                   (acc[mt][nt][3] + bv.y) * sc);
                    *(uint32_t*)&dq[r0 * D_ + colw]       = *(uint32_t*)&h0;
                    *(uint32_t*)&dq[(r0 + 8) * D_ + colw] = *(uint32_t*)&h1;
                }
        } else {
            // V: stage split values TRANSPOSED in smem, then coalesced stores.
            __nv_bfloat16* sm_h = (__nv_bfloat16*)gsm;
            __nv_bfloat16* sm_l = sm_h + 128 * 136;
#pragma unroll
            for (int mt = 0; mt < 4; mt++)
#pragma unroll
                for (int nt = 0; nt < 4; nt++) {
                    const int colw = wc * 32 + nt * 8 + cb;
                    float2 bv = *(const float2*)&bias[n0 + colw];
                    const int rl = wr * 64 + mt * 16 + g;
                    __nv_bfloat16 hh, ll;
                    split1(acc[mt][nt][0] + bv.x, hh, ll);
                    sm_h[colw * 136 + rl] = hh;       sm_l[colw * 136 + rl] = ll;
                    split1(acc[mt][nt][1] + bv.y, hh, ll);
                    sm_h[(colw + 1) * 136 + rl] = hh; sm_l[(colw + 1) * 136 + rl] = ll;
                    split1(acc[mt][nt][2] + bv.x, hh, ll);
                    sm_h[colw * 136 + rl + 8] = hh;       sm_l[colw * 136 + rl + 8] = ll;
                    split1(acc[mt][nt][3] + bv.y, hh, ll);
                    sm_h[(colw + 1) * 136 + rl + 8] = hh; sm_l[(colw + 1) * 136 + rl + 8] = ll;
                }
            __syncthreads();
            const int bidx  = (int)(m0 / S_);
            const int m0loc = (int)(m0 % S_);
#pragma unroll
            for (int it = 0; it < 8; it++) {
                int idx = tid + it * 256;
                int c = idx >> 4, sg = (idx & 15) * 8;
                int he = nn + c;
                int hh2 = he >> 6, e = he & 63;
                size_t ob = ((size_t)(bidx * H_ + hh2) * 64 + e) * S_ + m0loc + sg;
                *(uint4*)&g_vth[ob] = *(uint4*)&sm_h[c * 136 + sg];
                *(uint4*)&g_vtl[ob] = *(uint4*)&sm_l[c * 136 + sg];
            }
        }
    }
}

// ----------- causal flash attention: fp16 S, bf16x3 PV, pipelined -----------
// KV buffer = [K16 | Vh | Vl], each part 64x72 elems. 4 buffers.
#define PART_ 4608                 // elements per part (64*72)
#define BUF3_ (3 * PART_)          // elements per KV buffer (13824)
__global__ __launch_bounds__(256, 1) void attn_mma_kernel() {
    extern __shared__ __align__(16) char dsm[];
    __half* sm = (__half*)dsm;
    const uint32_t sb = smem_u32(sm);

    const int tid = threadIdx.x, wid = tid >> 5, lane = tid & 31;
    const int qt = gridDim.x - 1 - blockIdx.x;
    const int bh = blockIdx.y;
    const int b = bh / H_, h = bh % H_;
    const int q0 = qt * 128;

    // ---- Q tile (fp16, pre-scaled) -> smem staging ----
#pragma unroll
    for (int it = 0; it < 4; it++) {
        int idx = tid + it * 256;             // < 1024
        int r = idx >> 3, c8 = idx & 7;
        *(uint4*)&sm[r * 72 + c8 * 8] =
            *(const uint4*)&g_q16[(size_t)(b * S_ + q0 + r) * D_ + h * 64 + c8 * 8];
    }
    __syncthreads();

    uint32_t aQ[4][4];
    {
        const int row = wid * 16 + (lane & 15);
        const int c8 = (lane >> 4) * 8;
#pragma unroll
        for (int kk = 0; kk < 4; kk++)
            ldsm_x4(aQ[kk], sb + (row * 72 + kk * 16 + c8) * 2);
    }
    __syncthreads();   // Q area free

    float oacc[8][4] = {};
    float mrun[2] = {-1e30f, -1e30f}, lrun[2] = {0.0f, 0.0f};

    const int lrw = lane & 15;
    const int cb8 = (lane >> 4) * 8;
    const int ntiles = 2 * qt + 2;     // always even
    const int mask_from = 2 * qt;

    auto load_tile = [&](int kt, int bs) {
        const int k0 = kt * 64;
#pragma unroll
        for (int it = 0; it < 6; it++) {
            int idx = tid + it * 256;          // < 1536
            int part = idx >> 9;               // 0 K16, 1 Vh, 2 Vl
            int w = idx & 511;
            int row = w >> 3, c8 = w & 7;
            uint32_t dst = sb + (bs * BUF3_ + part * PART_ + row * 72 + c8 * 8) * 2;
            if (part == 0) {
                CP_ASYNC16(dst, &g_k16[(size_t)(b * S_ + k0 + row) * D_ + h * 64 + c8 * 8]);
            } else {
                const __nv_bfloat16* base = (part == 1) ? g_vth : g_vtl;
                CP_ASYNC16(dst, &base[((size_t)bh * 64 + row) * S_ + k0 + c8 * 8]);
            }
        }
        CP_COMMIT();
    };

    // S = Q K^T for tile kt (single fp16 MMA per atom)
    auto s_compute = [&](float (&sacc)[8][4], int kt) {
        const uint32_t kbase = sb + ((kt & 3) * BUF3_) * 2;
#pragma unroll
        for (int nt = 0; nt < 8; nt++)
#pragma unroll
            for (int e = 0; e < 4; e++) sacc[nt][e] = 0.0f;
#pragma unroll
        for (int kk = 0; kk < 4; kk++) {
#pragma unroll
            for (int np = 0; np < 4; np++) {
                uint32_t kb16[4];
                ldsm_x4(kb16, kbase + ((np * 16 + lrw) * 72 + kk * 16 + cb8) * 2);
#pragma unroll
                for (int ni = 0; ni < 2; ni++)
                    mma16816h(sacc[np * 2 + ni], aQ[kk], kb16[ni], kb16[ni + 2]);
            }
        }
    };

    // mask + streaming softmax (base 2) + P repack + PV (bf16x3)
    auto softmax_pv = [&](float (&sacc)[8][4], int kt) {
        const int k0 = kt * 64;
        if (kt >= mask_from) {
#pragma unroll
            for (int nt = 0; nt < 8; nt++)
#pragma unroll
                for (int e = 0; e < 4; e++) {
                    const int row = q0 + wid * 16 + (lane >> 2) + (e >> 1) * 8;
                    const int col = k0 + nt * 8 + (lane & 3) * 2 + (e & 1);
                    if (col > row) sacc[nt][e] = -1e30f;
                }
        }
#pragma unroll
        for (int rg = 0; rg < 2; rg++) {
            float mloc = -1e30f;
#pragma unroll
            for (int nt = 0; nt < 8; nt++)
                mloc = fmaxf(mloc, fmaxf(sacc[nt][rg * 2], sacc[nt][rg * 2 + 1]));
            mloc = fmaxf(mloc, __shfl_xor_sync(0xffffffffu, mloc, 1));
            mloc = fmaxf(mloc, __shfl_xor_sync(0xffffffffu, mloc, 2));
            const float mnew = fmaxf(mrun[rg], mloc);
            const float alpha = ex2f(mrun[rg] - mnew);
            float lloc = 0.0f;
#pragma unroll
            for (int nt = 0; nt < 8; nt++) {
                sacc[nt][rg * 2]     = ex2f(sacc[nt][rg * 2] - mnew);
                sacc[nt][rg * 2 + 1] = ex2f(sacc[nt][rg * 2 + 1] - mnew);
                lloc += sacc[nt][rg * 2] + sacc[nt][rg * 2 + 1];
            }
            lloc += __shfl_xor_sync(0xffffffffu, lloc, 1);
            lloc += __shfl_xor_sync(0xffffffffu, lloc, 2);
            lrun[rg] = lrun[rg] * alpha + lloc;
            mrun[rg] = mnew;
#pragma unroll
            for (int dt = 0; dt < 8; dt++) {
                oacc[dt][rg * 2]     *= alpha;
                oacc[dt][rg * 2 + 1] *= alpha;
            }
        }

        uint32_t aPh[4][4], aPl[4][4];
#pragma unroll
        for (int k2 = 0; k2 < 4; k2++) {
            split2(sacc[k2 * 2][0],     sacc[k2 * 2][1],     aPh[k2][0], aPl[k2][0]);
            split2(sacc[k2 * 2][2],     sacc[k2 * 2][3],     aPh[k2][1], aPl[k2][1]);
            split2(sacc[k2 * 2 + 1][0], sacc[k2 * 2 + 1][1], aPh[k2][2], aPl[k2][2]);
            split2(sacc[k2 * 2 + 1][2], sacc[k2 * 2 + 1][3], aPh[k2][3], aPl[k2][3]);
        }

        const uint32_t vbase = sb + ((kt & 3) * BUF3_ + PART_) * 2;
#pragma unroll
        for (int k2 = 0; k2 < 4; k2++) {
#pragma unroll
            for (int dp = 0; dp < 4; dp++) {
                uint32_t vbh[4], vbl[4];
                ldsm_x4(vbh, vbase + ((dp * 16 + lrw) * 72 + k2 * 16 + cb8) * 2);
                ldsm_x4(vbl, vbase + (PART_ + (dp * 16 + lrw) * 72 + k2 * 16 + cb8) * 2);
#pragma unroll
                for (int ni = 0; ni < 2; ni++) {
                    const int dt = dp * 2 + ni;
                    mma16816(oacc[dt], aPh[k2], vbh[ni], vbh[ni + 2]);
                    mma16816(oacc[dt], aPh[k2], vbl[ni], vbl[ni + 2]);
                    mma16816(oacc[dt], aPl[k2], vbh[ni], vbh[ni + 2]);
                }
            }
        }
    };

    load_tile(0, 0);
    load_tile(1, 1);

    float sA[8][4], sB[8][4];

    for (int kt2 = 0; kt2 < ntiles; kt2 += 2) {
        CP_WAIT(1);
        __syncthreads();
        if (kt2 + 2 < ntiles) load_tile(kt2 + 2, (kt2 + 2) & 3);
        s_compute(sA, kt2);
        if (kt2 > 0) softmax_pv(sB, kt2 - 1);

        if (kt2 + 2 < ntiles) CP_WAIT(1); else CP_WAIT(0);
        __syncthreads();
        if (kt2 + 3 < ntiles) load_tile(kt2 + 3, (kt2 + 3) & 3);
        s_compute(sB, kt2 + 1);
        softmax_pv(sA, kt2);
    }
    softmax_pv(sB, ntiles - 1);

    // ---- epilogue: z = O / l, split bf16 hi/lo ----
#pragma unroll
    for (int rg = 0; rg < 2; rg++) {
        const float inv = 1.0f / lrun[rg];
        const int row = q0 + wid * 16 + (lane >> 2) + rg * 8;
#pragma unroll
        for (int dt = 0; dt < 8; dt++) {
            const size_t o = (size_t)(b * S_ + row) * D_ + h * 64 + dt * 8 + (lane & 3) * 2;
            uint32_t hp, lp;
            split2(oacc[dt][rg * 2] * inv, oacc[dt][rg * 2 + 1] * inv, hp, lp);
            *(uint32_t*)&g_zh[o] = hp;
            *(uint32_t*)&g_zl[o] = lp;
        }
    }
}

// --------------------------------- launch ----------------------------------
extern "C" void kernel_launch(void* const* d_in, const int* in_sizes, int n_in,
                              void* d_out, int out_size) {
    const float* X  = (const float*)d_in[0];
    const float* Wq = (const float*)d_in[1];
    const float* Wk = (const float*)d_in[2];
    const float* Wv = (const float*)d_in[3];
    const float* Wo = (const float*)d_in[4];
    const float* bq = (const float*)d_in[5];
    const float* bk = (const float*)d_in[6];
    const float* bv = (const float*)d_in[7];
    const float* bo = (const float*)d_in[8];
    float* out = (float*)d_out;

    const int attn_smem = 4 * BUF3_ * 2;    // 110592 B
    const int gemm_smem = 2 * GSTG_ * 2;    // 81920 B
    static bool attr_set = false;
    if (!attr_set) {
        cudaFuncSetAttribute(attn_mma_kernel,
                             cudaFuncAttributeMaxDynamicSharedMemorySize, attn_smem);
        cudaFuncSetAttribute(gemm_mma_kernel<0>,
                             cudaFuncAttributeMaxDynamicSharedMemorySize, gemm_smem);
        cudaFuncSetAttribute(gemm_mma_kernel<1>,
                             cudaFuncAttributeMaxDynamicSharedMemorySize, gemm_smem);
        attr_set = true;
    }

    static __nv_bfloat16 *xh = nullptr, *xl, *zh, *zl, *wth, *wtl, *woh, *wol;
    static float *fb;
    if (!xh) {
        cudaGetSymbolAddress((void**)&xh,  g_xh);
        cudaGetSymbolAddress((void**)&xl,  g_xl);
        cudaGetSymbolAddress((void**)&zh,  g_zh);
        cudaGetSymbolAddress((void**)&zl,  g_zl);
        cudaGetSymbolAddress((void**)&wth, g_wth);
        cudaGetSymbolAddress((void**)&wtl, g_wtl);
        cudaGetSymbolAddress((void**)&woh, g_woh);
        cudaGetSymbolAddress((void**)&wol, g_wol);
        cudaGetSymbolAddress((void**)&fb,  g_fb);
    }

    // 1) conversions
    split_kernel<<<(M_ * D_) / (256 * 8), 256>>>(X, xh, xl, M_ * D_);
    trans_qkv_kernel<<<dim3(D_ / 64, 3 * H_), 256>>>(Wq, Wk, Wv, bq, bk, bv);
    trans_wo_kernel<<<dim3(D_ / 64, D_ / 64), 256>>>(Wo);

    // 2) fused QKV projection -> q/k fp16 + V transposed split bf16
    gemm_mma_kernel<1><<<dim3(NF_ / 128, M_ / 128), 256, gemm_smem>>>(
        xh, xl, wth, wtl, nullptr, 0, fb);

    // 3) causal attention (fp16 S, bf16x3 PV, pipelined)
    attn_mma_kernel<<<dim3(S_ / 128, B_ * H_), 256, attn_smem>>>();

    // 4) output projection (bf16x3)
    gemm_mma_kernel<0><<<dim3(D_ / 128, M_ / 128), 256, gemm_smem>>>(
        zh, zl, woh, wol, out, D_, bo);
}

// round 17
// speedup vs baseline: 1.4876x; 1.1595x over previous
#include <cuda_runtime.h>
#include <cuda_bf16.h>
#include <cuda_fp16.h>
#include <cstdint>

#define B_  4
#define S_  2048
#define D_  768
#define H_  12
#define M_  (B_ * S_)     // 8192
#define NF_ (3 * D_)      // 2304

// ------------------------- device scratch (no allocs) -----------------------
__device__ __nv_bfloat16  g_xh [(size_t)M_ * D_];    // residual hi/lo
__device__ __nv_bfloat16  g_xl [(size_t)M_ * D_];
__device__ __half         g_q16[(size_t)M_ * D_];    // q (pre-scaled) fp16
__device__ __half         g_k16[(size_t)M_ * D_];    // k fp16
__device__ __half         g_v16t[(size_t)B_ * H_ * 64 * S_]; // v^T fp16
__device__ __nv_bfloat16  g_zh [(size_t)M_ * D_];    // attention out hi/lo
__device__ __nv_bfloat16  g_zl [(size_t)M_ * D_];
__device__ __nv_bfloat16  g_wth[(size_t)NF_ * D_];   // W_qkv^T  [n][d] hi/lo
__device__ __nv_bfloat16  g_wtl[(size_t)NF_ * D_];
__device__ __nv_bfloat16  g_woh[(size_t)D_ * D_];    // W_O^T hi/lo
__device__ __nv_bfloat16  g_wol[(size_t)D_ * D_];
__device__ float          g_fb [NF_];                // fused qkv bias

// ------------------------------ PTX helpers --------------------------------
__device__ __forceinline__ uint32_t smem_u32(const void* p) {
    uint32_t a;
    asm("{ .reg .u64 t; cvta.to.shared.u64 t, %1; cvt.u32.u64 %0, t; }"
        : "=r"(a) : "l"(p));
    return a;
}
__device__ __forceinline__ void ldsm_x4(uint32_t* r, uint32_t addr) {
    asm volatile("ldmatrix.sync.aligned.m8n8.x4.shared.b16 {%0,%1,%2,%3}, [%4];"
                 : "=r"(r[0]), "=r"(r[1]), "=r"(r[2]), "=r"(r[3]) : "r"(addr));
}
__device__ __forceinline__ void mma16816(float* c, const uint32_t* a,
                                         uint32_t b0, uint32_t b1) {
    asm volatile(
        "mma.sync.aligned.m16n8k16.row.col.f32.bf16.bf16.f32 "
        "{%0,%1,%2,%3}, {%4,%5,%6,%7}, {%8,%9}, {%0,%1,%2,%3};"
        : "+f"(c[0]), "+f"(c[1]), "+f"(c[2]), "+f"(c[3])
        : "r"(a[0]), "r"(a[1]), "r"(a[2]), "r"(a[3]), "r"(b0), "r"(b1));
}
__device__ __forceinline__ void mma16816h(float* c, const uint32_t* a,
                                          uint32_t b0, uint32_t b1) {
    asm volatile(
        "mma.sync.aligned.m16n8k16.row.col.f32.f16.f16.f32 "
        "{%0,%1,%2,%3}, {%4,%5,%6,%7}, {%8,%9}, {%0,%1,%2,%3};"
        : "+f"(c[0]), "+f"(c[1]), "+f"(c[2]), "+f"(c[3])
        : "r"(a[0]), "r"(a[1]), "r"(a[2]), "r"(a[3]), "r"(b0), "r"(b1));
}
__device__ __forceinline__ float ex2f(float x) {
    float y;
    asm("ex2.approx.f32 %0, %1;" : "=f"(y) : "f"(x));
    return y;
}
__device__ __forceinline__ void split2(float a, float b, uint32_t& hi, uint32_t& lo) {
    __nv_bfloat16 ha = __float2bfloat16(a), hb = __float2bfloat16(b);
    __nv_bfloat16 la = __float2bfloat16(a - __bfloat162float(ha));
    __nv_bfloat16 lb = __float2bfloat16(b - __bfloat162float(hb));
    __nv_bfloat162 hp = {ha, hb}, lp = {la, lb};
    hi = *(uint32_t*)&hp; lo = *(uint32_t*)&lp;
}
#define CP_ASYNC16(dst, src) \
    asm volatile("cp.async.cg.shared.global [%0], [%1], 16;" :: "r"(dst), "l"(src))
#define CP_COMMIT() asm volatile("cp.async.commit_group;" ::: "memory")
#define CP_WAIT(n)  asm volatile("cp.async.wait_group %0;" :: "n"(n) : "memory")

// --------------------------- conversion kernels ----------------------------
__global__ void split_kernel(const float* __restrict__ src,
                             __nv_bfloat16* __restrict__ dh,
                             __nv_bfloat16* __restrict__ dl, int n) {
    int i8 = (blockIdx.x * 256 + threadIdx.x) * 8;
    if (i8 >= n) return;
    float4 v0 = *(const float4*)&src[i8];
    float4 v1 = *(const float4*)&src[i8 + 4];
    float v[8] = {v0.x, v0.y, v0.z, v0.w, v1.x, v1.y, v1.z, v1.w};
    __align__(16) __nv_bfloat16 h[8], l[8];
#pragma unroll
    for (int j = 0; j < 8; j++) {
        h[j] = __float2bfloat16(v[j]);
        l[j] = __float2bfloat16(v[j] - __bfloat162float(h[j]));
    }
    *(uint4*)&dh[i8] = *(uint4*)h;
    *(uint4*)&dl[i8] = *(uint4*)l;
}

__device__ __forceinline__ void trans_tile(const float* src, int src_ld,
                                           __nv_bfloat16* dh, __nv_bfloat16* dl,
                                           int dst_ld, int r0, int c0, int base) {
    __shared__ float ts[64 * 65];
    const int tid = threadIdx.x;
#pragma unroll
    for (int it = 0; it < 16; it++) {
        int flat = tid + it * 256;
        int i = flat >> 6, c = flat & 63;
        ts[c * 65 + i] = src[(size_t)(r0 + i) * src_ld + c0 + c];
    }
    __syncthreads();
#pragma unroll
    for (int it = 0; it < 8; it++) {
        int flat = tid + it * 256;
        int c = flat >> 5, rj = flat & 31;
        uint32_t hp, lp;
        split2(ts[c * 65 + rj * 2], ts[c * 65 + rj * 2 + 1], hp, lp);
        size_t o = (size_t)(base + c0 + c) * dst_ld + r0 + rj * 2;
        *(uint32_t*)&dh[o] = hp;
        *(uint32_t*)&dl[o] = lp;
    }
}

__global__ void trans_qkv_kernel(const float* __restrict__ Wq,
                                 const float* __restrict__ Wk,
                                 const float* __restrict__ Wv,
                                 const float* __restrict__ bq,
                                 const float* __restrict__ bk,
                                 const float* __restrict__ bv) {
    const int by = blockIdx.y;
    const int t = by / H_, h = by % H_;
    if (blockIdx.x == 0 && threadIdx.x < 64) {
        const float* bp = (t == 0) ? bq : (t == 1) ? bk : bv;
        g_fb[t * D_ + h * 64 + threadIdx.x] = bp[h * 64 + threadIdx.x];
    }
    const float* src = ((t == 0) ? Wq : (t == 1) ? Wk : Wv) + (size_t)h * D_ * 64;
    trans_tile(src, 64, g_wth, g_wtl, D_, blockIdx.x * 64, 0, t * D_ + h * 64);
}
__global__ void trans_wo_kernel(const float* __restrict__ Wo) {
    trans_tile(Wo, D_, g_woh, g_wol, D_, blockIdx.x * 64, blockIdx.y * 64, 0);
}

// ------------------------ mma.sync bf16x3 GEMM ------------------------------
// occ 2, cp.async double-buffered. MODE 0: fp32 out + bias.
// MODE 1: q/k fp16 (q pre-scaled 0.125*log2e); V transposed fp16 via smem.
#define GP_   5120                 // elements per part (128*40)
#define GSTG_ (4 * GP_)            // elements per stage
#define QSCALE_ 0.180336880f       // 0.125 * log2(e)
template <int MODE>
__global__ __launch_bounds__(256, 2)
void gemm_mma_kernel(const __nv_bfloat16* __restrict__ Ah,
                     const __nv_bfloat16* __restrict__ Al,
                     const __nv_bfloat16* __restrict__ Bh,
                     const __nv_bfloat16* __restrict__ Bl,
                     float* __restrict__ out, int ld_out,
                     const float* __restrict__ bias) {
    extern __shared__ __align__(16) char gsm[];
    const uint32_t sb = smem_u32(gsm);

    const int tid  = threadIdx.x;
    const int wid  = tid >> 5;
    const int lane = tid & 31;
    const int wr   = wid >> 2;
    const int wc   = wid & 3;
    const size_t m0 = blockIdx.y * 128;
    const size_t n0 = blockIdx.x * 128;

    const __nv_bfloat16* srcs[4] = {Ah, Al, Bh, Bl};
    const size_t rbase[4] = {m0, m0, n0, n0};

    auto load_st = [&](int kt, int st) {
        const int k0 = kt * 32;
#pragma unroll
        for (int it = 0; it < 8; it++) {
            int idx = tid + it * 256;
            int part = idx >> 9;
            int w = idx & 511;
            int row = w >> 2, c8 = w & 3;
            uint32_t dst = sb + (st * GSTG_ + part * GP_ + row * 40 + c8 * 8) * 2;
            const __nv_bfloat16* src =
                &srcs[part][(rbase[part] + row) * D_ + k0 + c8 * 8];
            CP_ASYNC16(dst, src);
        }
        CP_COMMIT();
    };

    float acc[4][4][4] = {};

    const int lrow = lane & 15;
    const int lcol = (lane >> 4) * 8;

    load_st(0, 0);

    for (int kt = 0; kt < 24; kt++) {
        const int st = kt & 1;
        if (kt < 23) { load_st(kt + 1, 1 - st); CP_WAIT(1); }
        else         { CP_WAIT(0); }
        __syncthreads();

        const uint32_t s0 = sb + (st * GSTG_) * 2;
#pragma unroll
        for (int ks = 0; ks < 2; ks++) {
            const int kb = ks * 16;
            const uint32_t arow = s0 + ((wr * 64 + lrow) * 40 + kb + lcol) * 2;
            const uint32_t brow = s0 + ((wc * 32 + lrow) * 40 + kb + lcol) * 2;

            uint32_t aF[4][4], bFh[2][4], bF2[2][4];
#pragma unroll
            for (int mt = 0; mt < 4; mt++)
                ldsm_x4(aF[mt], arow + (0 * GP_ + mt * 16 * 40) * 2);
#pragma unroll
            for (int np = 0; np < 2; np++)
                ldsm_x4(bFh[np], brow + (2 * GP_ + np * 16 * 40) * 2);
#pragma unroll
            for (int mt = 0; mt < 4; mt++)
#pragma unroll
                for (int nt = 0; nt < 4; nt++)
                    mma16816(acc[mt][nt], aF[mt], bFh[nt >> 1][nt & 1],
                             bFh[nt >> 1][(nt & 1) + 2]);
#pragma unroll
            for (int np = 0; np < 2; np++)
                ldsm_x4(bF2[np], brow + (3 * GP_ + np * 16 * 40) * 2);
#pragma unroll
            for (int mt = 0; mt < 4; mt++)
#pragma unroll
                for (int nt = 0; nt < 4; nt++)
                    mma16816(acc[mt][nt], aF[mt], bF2[nt >> 1][nt & 1],
                             bF2[nt >> 1][(nt & 1) + 2]);
#pragma unroll
            for (int mt = 0; mt < 4; mt++)
                ldsm_x4(aF[mt], arow + (1 * GP_ + mt * 16 * 40) * 2);
#pragma unroll
            for (int mt = 0; mt < 4; mt++)
#pragma unroll
                for (int nt = 0; nt < 4; nt++)
                    mma16816(acc[mt][nt], aF[mt], bFh[nt >> 1][nt & 1],
                             bFh[nt >> 1][(nt & 1) + 2]);
        }
        __syncthreads();
    }

    const int g = lane >> 2;
    const int cb = (lane & 3) * 2;

    if (MODE == 0) {
#pragma unroll
        for (int mt = 0; mt < 4; mt++)
#pragma unroll
            for (int nt = 0; nt < 4; nt++) {
                const size_t col = n0 + wc * 32 + nt * 8 + cb;
                float2 bv = *(const float2*)&bias[col];
                const size_t r0 = m0 + wr * 64 + mt * 16 + g;
                float2 v0 = {acc[mt][nt][0] + bv.x, acc[mt][nt][1] + bv.y};
                float2 v1 = {acc[mt][nt][2] + bv.x, acc[mt][nt][3] + bv.y};
                *(float2*)&out[r0 * ld_out + col]       = v0;
                *(float2*)&out[(r0 + 8) * ld_out + col] = v1;
            }
    } else {
        const int t  = (int)(n0 / D_);
        const int nn = (int)(n0 - t * D_);
        if (t < 2) {
            __half* dq = (t == 0) ? g_q16 : g_k16;
            const float sc = (t == 0) ? QSCALE_ : 1.0f;
#pragma unroll
            for (int mt = 0; mt < 4; mt++)
#pragma unroll
                for (int nt = 0; nt < 4; nt++) {
                    const int colw = nn + wc * 32 + nt * 8 + cb;
                    float2 bv = *(const float2*)&bias[n0 + wc * 32 + nt * 8 + cb];
                    const size_t r0 = m0 + wr * 64 + mt * 16 + g;
                    __half2 h0 = __floats2half2_rn((acc[mt][nt][0] + bv.x) * sc,
                                                   (acc[mt][nt][1] + bv.y) * sc);
                    __half2 h1 = __floats2half2_rn((acc[mt][nt][2] + bv.x) * sc,
                                                   (acc[mt][nt][3] + bv.y) * sc);
                    *(uint32_t*)&dq[r0 * D_ + colw]       = *(uint32_t*)&h0;
                    *(uint32_t*)&dq[(r0 + 8) * D_ + colw] = *(uint32_t*)&h1;
                }
        } else {
            // V: stage fp16 TRANSPOSED in smem, then coalesced stores.
            __half* sm16 = (__half*)gsm;   // [col 0..127][row 0..127], stride 136
#pragma unroll
            for (int mt = 0; mt < 4; mt++)
#pragma unroll
                for (int nt = 0; nt < 4; nt++) {
                    const int colw = wc * 32 + nt * 8 + cb;
                    float2 bv = *(const float2*)&bias[n0 + colw];
                    const int rl = wr * 64 + mt * 16 + g;
                    sm16[colw * 136 + rl]           = __float2half(acc[mt][nt][0] + bv.x);
                    sm16[(colw + 1) * 136 + rl]     = __float2half(acc[mt][nt][1] + bv.y);
                    sm16[colw * 136 + rl + 8]       = __float2half(acc[mt][nt][2] + bv.x);
                    sm16[(colw + 1) * 136 + rl + 8] = __float2half(acc[mt][nt][3] + bv.y);
                }
            __syncthreads();
            const int bidx  = (int)(m0 / S_);
            const int m0loc = (int)(m0 % S_);
#pragma unroll
            for (int it = 0; it < 8; it++) {
                int idx = tid + it * 256;          // < 2048
                int c = idx >> 4, sg = (idx & 15) * 8;
                int he = nn + c;
                int hh2 = he >> 6, e = he & 63;
                size_t ob = ((size_t)(bidx * H_ + hh2) * 64 + e) * S_ + m0loc + sg;
                *(uint4*)&g_v16t[ob] = *(uint4*)&sm16[c * 136 + sg];
            }
        }
    }
}

// ----------- causal flash attention: fp16 S + fp16 PV, pipelined ------------
// KV buffer = [K16 | V16t], each part 64x72 fp16. 4 buffers (73728 B).
#define PART_ 4608                 // elements per part (64*72)
#define BUF2_ (2 * PART_)          // elements per KV buffer
__global__ __launch_bounds__(256, 1) void attn_mma_kernel() {
    extern __shared__ __align__(16) char dsm[];
    __half* sm = (__half*)dsm;
    const uint32_t sb = smem_u32(sm);

    const int tid = threadIdx.x, wid = tid >> 5, lane = tid & 31;
    const int qt = gridDim.x - 1 - blockIdx.x;
    const int bh = blockIdx.y;
    const int b = bh / H_, h = bh % H_;
    const int q0 = qt * 128;

    // ---- Q tile (fp16, pre-scaled) -> smem staging ----
#pragma unroll
    for (int it = 0; it < 4; it++) {
        int idx = tid + it * 256;             // < 1024
        int r = idx >> 3, c8 = idx & 7;
        *(uint4*)&sm[r * 72 + c8 * 8] =
            *(const uint4*)&g_q16[(size_t)(b * S_ + q0 + r) * D_ + h * 64 + c8 * 8];
    }
    __syncthreads();

    uint32_t aQ[4][4];
    {
        const int row = wid * 16 + (lane & 15);
        const int c8 = (lane >> 4) * 8;
#pragma unroll
        for (int kk = 0; kk < 4; kk++)
            ldsm_x4(aQ[kk], sb + (row * 72 + kk * 16 + c8) * 2);
    }
    __syncthreads();   // Q area free

    float oacc[8][4] = {};
    float mrun[2] = {-1e30f, -1e30f}, lrun[2] = {0.0f, 0.0f};

    const int lrw = lane & 15;
    const int cb8 = (lane >> 4) * 8;
    const int ntiles = 2 * qt + 2;     // always even
    const int mask_from = 2 * qt;

    auto load_tile = [&](int kt, int bs) {
        const int k0 = kt * 64;
#pragma unroll
        for (int it = 0; it < 4; it++) {
            int idx = tid + it * 256;          // < 1024
            int part = idx >> 9;               // 0 K16, 1 V16t
            int w = idx & 511;
            int row = w >> 3, c8 = w & 7;
            uint32_t dst = sb + (bs * BUF2_ + part * PART_ + row * 72 + c8 * 8) * 2;
            if (part == 0) {
                CP_ASYNC16(dst, &g_k16[(size_t)(b * S_ + k0 + row) * D_ + h * 64 + c8 * 8]);
            } else {
                CP_ASYNC16(dst, &g_v16t[((size_t)bh * 64 + row) * S_ + k0 + c8 * 8]);
            }
        }
        CP_COMMIT();
    };

    // S = Q K^T (fp16, single MMA per atom)
    auto s_compute = [&](float (&sacc)[8][4], int kt) {
        const uint32_t kbase = sb + ((kt & 3) * BUF2_) * 2;
#pragma unroll
        for (int nt = 0; nt < 8; nt++)
#pragma unroll
            for (int e = 0; e < 4; e++) sacc[nt][e] = 0.0f;
#pragma unroll
        for (int kk = 0; kk < 4; kk++) {
#pragma unroll
            for (int np = 0; np < 4; np++) {
                uint32_t kb16[4];
                ldsm_x4(kb16, kbase + ((np * 16 + lrw) * 72 + kk * 16 + cb8) * 2);
#pragma unroll
                for (int ni = 0; ni < 2; ni++)
                    mma16816h(sacc[np * 2 + ni], aQ[kk], kb16[ni], kb16[ni + 2]);
            }
        }
    };

    // mask + streaming softmax (base 2) + fp16 P repack + fp16 PV
    auto softmax_pv = [&](float (&sacc)[8][4], int kt) {
        const int k0 = kt * 64;
        if (kt >= mask_from) {
#pragma unroll
            for (int nt = 0; nt < 8; nt++)
#pragma unroll
                for (int e = 0; e < 4; e++) {
                    const int row = q0 + wid * 16 + (lane >> 2) + (e >> 1) * 8;
                    const int col = k0 + nt * 8 + (lane & 3) * 2 + (e & 1);
                    if (col > row) sacc[nt][e] = -1e30f;
                }
        }
#pragma unroll
        for (int rg = 0; rg < 2; rg++) {
            float mloc = -1e30f;
#pragma unroll
            for (int nt = 0; nt < 8; nt++)
                mloc = fmaxf(mloc, fmaxf(sacc[nt][rg * 2], sacc[nt][rg * 2 + 1]));
            mloc = fmaxf(mloc, __shfl_xor_sync(0xffffffffu, mloc, 1));
            mloc = fmaxf(mloc, __shfl_xor_sync(0xffffffffu, mloc, 2));
            const float mnew = fmaxf(mrun[rg], mloc);
            const float alpha = ex2f(mrun[rg] - mnew);
            float lloc = 0.0f;
#pragma unroll
            for (int nt = 0; nt < 8; nt++) {
                sacc[nt][rg * 2]     = ex2f(sacc[nt][rg * 2] - mnew);
                sacc[nt][rg * 2 + 1] = ex2f(sacc[nt][rg * 2 + 1] - mnew);
                lloc += sacc[nt][rg * 2] + sacc[nt][rg * 2 + 1];
            }
            lloc += __shfl_xor_sync(0xffffffffu, lloc, 1);
            lloc += __shfl_xor_sync(0xffffffffu, lloc, 2);
            lrun[rg] = lrun[rg] * alpha + lloc;
            mrun[rg] = mnew;
#pragma unroll
            for (int dt = 0; dt < 8; dt++) {
                oacc[dt][rg * 2]     *= alpha;
                oacc[dt][rg * 2 + 1] *= alpha;
            }
        }

        // P -> fp16 A-fragments
        uint32_t aP[4][4];
#pragma unroll
        for (int k2 = 0; k2 < 4; k2++) {
            __half2 p0 = __floats2half2_rn(sacc[k2 * 2][0],     sacc[k2 * 2][1]);
            __half2 p1 = __floats2half2_rn(sacc[k2 * 2][2],     sacc[k2 * 2][3]);
            __half2 p2 = __floats2half2_rn(sacc[k2 * 2 + 1][0], sacc[k2 * 2 + 1][1]);
            __half2 p3 = __floats2half2_rn(sacc[k2 * 2 + 1][2], sacc[k2 * 2 + 1][3]);
            aP[k2][0] = *(uint32_t*)&p0;
            aP[k2][1] = *(uint32_t*)&p1;
            aP[k2][2] = *(uint32_t*)&p2;
            aP[k2][3] = *(uint32_t*)&p3;
        }

        const uint32_t vbase = sb + ((kt & 3) * BUF2_ + PART_) * 2;
#pragma unroll
        for (int k2 = 0; k2 < 4; k2++) {
#pragma unroll
            for (int dp = 0; dp < 4; dp++) {
                uint32_t vb[4];
                ldsm_x4(vb, vbase + ((dp * 16 + lrw) * 72 + k2 * 16 + cb8) * 2);
#pragma unroll
                for (int ni = 0; ni < 2; ni++)
                    mma16816h(oacc[dp * 2 + ni], aP[k2], vb[ni], vb[ni + 2]);
            }
        }
    };

    load_tile(0, 0);
    load_tile(1, 1);

    float sA[8][4], sB[8][4];

    for (int kt2 = 0; kt2 < ntiles; kt2 += 2) {
        CP_WAIT(1);
        __syncthreads();
        if (kt2 + 2 < ntiles) load_tile(kt2 + 2, (kt2 + 2) & 3);
        s_compute(sA, kt2);
        if (kt2 > 0) softmax_pv(sB, kt2 - 1);

        if (kt2 + 2 < ntiles) CP_WAIT(1); else CP_WAIT(0);
        __syncthreads();
        if (kt2 + 3 < ntiles) load_tile(kt2 + 3, (kt2 + 3) & 3);
        s_compute(sB, kt2 + 1);
        softmax_pv(sA, kt2);
    }
    softmax_pv(sB, ntiles - 1);

    // ---- epilogue: z = O / l, split bf16 hi/lo (out-proj stays bf16x3) ----
#pragma unroll
    for (int rg = 0; rg < 2; rg++) {
        const float inv = 1.0f / lrun[rg];
        const int row = q0 + wid * 16 + (lane >> 2) + rg * 8;
#pragma unroll
        for (int dt = 0; dt < 8; dt++) {
            const size_t o = (size_t)(b * S_ + row) * D_ + h * 64 + dt * 8 + (lane & 3) * 2;
            uint32_t hp, lp;
            split2(oacc[dt][rg * 2] * inv, oacc[dt][rg * 2 + 1] * inv, hp, lp);
            *(uint32_t*)&g_zh[o] = hp;
            *(uint32_t*)&g_zl[o] = lp;
        }
    }
}

// --------------------------------- launch ----------------------------------
extern "C" void kernel_launch(void* const* d_in, const int* in_sizes, int n_in,
                              void* d_out, int out_size) {
    const float* X  = (const float*)d_in[0];
    const float* Wq = (const float*)d_in[1];
    const float* Wk = (const float*)d_in[2];
    const float* Wv = (const float*)d_in[3];
    const float* Wo = (const float*)d_in[4];
    const float* bq = (const float*)d_in[5];
    const float* bk = (const float*)d_in[6];
    const float* bv = (const float*)d_in[7];
    const float* bo = (const float*)d_in[8];
    float* out = (float*)d_out;

    const int attn_smem = 4 * BUF2_ * 2;    // 73728 B
    const int gemm_smem = 2 * GSTG_ * 2;    // 81920 B
    static bool attr_set = false;
    if (!attr_set) {
        cudaFuncSetAttribute(attn_mma_kernel,
                             cudaFuncAttributeMaxDynamicSharedMemorySize, attn_smem);
        cudaFuncSetAttribute(gemm_mma_kernel<0>,
                             cudaFuncAttributeMaxDynamicSharedMemorySize, gemm_smem);
        cudaFuncSetAttribute(gemm_mma_kernel<1>,
                             cudaFuncAttributeMaxDynamicSharedMemorySize, gemm_smem);
        attr_set = true;
    }

    static __nv_bfloat16 *xh = nullptr, *xl, *zh, *zl, *wth, *wtl, *woh, *wol;
    static float *fb;
    if (!xh) {
        cudaGetSymbolAddress((void**)&xh,  g_xh);
        cudaGetSymbolAddress((void**)&xl,  g_xl);
        cudaGetSymbolAddress((void**)&zh,  g_zh);
        cudaGetSymbolAddress((void**)&zl,  g_zl);
        cudaGetSymbolAddress((void**)&wth, g_wth);
        cudaGetSymbolAddress((void**)&wtl, g_wtl);
        cudaGetSymbolAddress((void**)&woh, g_woh);
        cudaGetSymbolAddress((void**)&wol, g_wol);
        cudaGetSymbolAddress((void**)&fb,  g_fb);
    }

    // 1) conversions
    split_kernel<<<(M_ * D_) / (256 * 8), 256>>>(X, xh, xl, M_ * D_);
    trans_qkv_kernel<<<dim3(D_ / 64, 3 * H_), 256>>>(Wq, Wk, Wv, bq, bk, bv);
    trans_wo_kernel<<<dim3(D_ / 64, D_ / 64), 256>>>(Wo);

    // 2) fused QKV projection -> q/k fp16 + V transposed fp16
    gemm_mma_kernel<1><<<dim3(NF_ / 128, M_ / 128), 256, gemm_smem>>>(
        xh, xl, wth, wtl, nullptr, 0, fb);

    // 3) causal attention (fp16 S + fp16 PV, pipelined)
    attn_mma_kernel<<<dim3(S_ / 128, B_ * H_), 256, attn_smem>>>();

    // 4) output projection (bf16x3)
    gemm_mma_kernel<0><<<dim3(D_ / 128, M_ / 128), 256, gemm_smem>>>(
        zh, zl, woh, wol, out, D_, bo);
}